// round 5
// baseline (speedup 1.0000x reference)
#include <cuda_runtime.h>
#include <cstdint>

// R4b (rerun after infra failure): stream via cp.async.bulk (UBLKCP) instead of
// per-warp LDG/STG. Three structurally different LDG kernels (scalar cosf,
// poly MLP=1, MUFU MLP=4) all paced at ~2.2TB/s read with every pipe <28%
// busy -> suspect per-SM LDG in-flight cap. Each block bulk-copies a 16KB
// x-tile to smem, computes cos-products with MUFU, bulk-stores the 16KB
// out-tile. 1024 blocks = exact cover of 2^20 rows, single wave.
//
// Math: RZ phases drop out (params unused); CNOT chain is an XOR-linear
// permutation; out = [c1c2c3, c0c1, c0c1c2, c0c1c2c3], c_j = cos(x_j).

#define BLOCK 256
#define F4_PER_BLOCK 1024            // float4 per tile
#define TILE_BYTES 16384             // 16 KB

__device__ __forceinline__ uint32_t smem_u32(const void* p) {
    uint32_t a;
    asm("{ .reg .u64 t; cvta.to.shared.u64 t, %1; cvt.u32.u64 %0, t; }"
        : "=r"(a) : "l"(p));
    return a;
}

__global__ void __launch_bounds__(BLOCK)
_VariationalQHead_65481071396152_kernel(const float4* __restrict__ x,
                                        float4* __restrict__ out)
{
    __shared__ __align__(128) float4 s_in[F4_PER_BLOCK];
    __shared__ __align__(128) float4 s_out[F4_PER_BLOCK];
    __shared__ __align__(8) unsigned long long mbar;

    const int t = threadIdx.x;
    const uint32_t mbar_a = smem_u32(&mbar);

    if (t == 0) {
        asm volatile("mbarrier.init.shared.b64 [%0], 1;" :: "r"(mbar_a) : "memory");
        asm volatile("fence.proxy.async.shared::cta;" ::: "memory");
        asm volatile("mbarrier.arrive.expect_tx.shared.b64 _, [%0], %1;"
                     :: "r"(mbar_a), "r"((uint32_t)TILE_BYTES) : "memory");
        const char* src = (const char*)(x + (size_t)blockIdx.x * F4_PER_BLOCK);
        asm volatile("cp.async.bulk.shared::cta.global.mbarrier::complete_tx::bytes "
                     "[%0], [%1], %2, [%3];"
                     :: "r"(smem_u32(s_in)), "l"(src),
                        "r"((uint32_t)TILE_BYTES), "r"(mbar_a) : "memory");
    }
    __syncthreads();

    // Wait for bulk load completion (first use -> phase parity 0).
    {
        uint32_t done;
        asm volatile(
            "{\n\t"
            ".reg .pred p;\n\t"
            "mbarrier.try_wait.parity.acquire.cta.shared::cta.b64 p, [%1], 0;\n\t"
            "selp.b32 %0, 1, 0, p;\n\t"
            "}" : "=r"(done) : "r"(mbar_a) : "memory");
        if (!done) {
            asm volatile(
                "{\n\t"
                ".reg .pred P1;\n\t"
                "WL_%=:\n\t"
                "mbarrier.try_wait.parity.acquire.cta.shared::cta.b64 P1, [%0], 0, 0x989680;\n\t"
                "@P1 bra.uni WD_%=;\n\t"
                "bra.uni WL_%=;\n\t"
                "WD_%=:\n\t"
                "}" :: "r"(mbar_a) : "memory");
        }
    }

#pragma unroll
    for (int k = 0; k < F4_PER_BLOCK / BLOCK; k++) {
        float4 v = s_in[t + k * BLOCK];
        float c0 = __cosf(v.x);
        float c1 = __cosf(v.y);
        float c2 = __cosf(v.z);
        float c3 = __cosf(v.w);
        float c01  = c0 * c1;
        float c012 = c01 * c2;
        float4 o;
        o.x = c1 * c2 * c3;
        o.y = c01;
        o.z = c012;
        o.w = c012 * c3;
        s_out[t + k * BLOCK] = o;
    }

    __syncthreads();               // all STS complete, CTA-visible
    if (t == 0) {
        asm volatile("fence.proxy.async.shared::cta;" ::: "memory");
        char* dst = (char*)(out + (size_t)blockIdx.x * F4_PER_BLOCK);
        asm volatile("cp.async.bulk.global.shared::cta.bulk_group [%0], [%1], %2;"
                     :: "l"(dst), "r"(smem_u32(s_out)),
                        "r"((uint32_t)TILE_BYTES) : "memory");
        asm volatile("cp.async.bulk.commit_group;" ::: "memory");
        asm volatile("cp.async.bulk.wait_group 0;" ::: "memory");
    }
}

// Scalar tail fallback (dataset: 1048576 % 1024 == 0, so normally unused).
__global__ void _VQH_tail_kernel(const float4* __restrict__ x,
                                 float4* __restrict__ out, int start, int n)
{
    int i = start + blockIdx.x * blockDim.x + threadIdx.x;
    if (i < n) {
        float4 v = x[i];
        float c0 = __cosf(v.x), c1 = __cosf(v.y), c2 = __cosf(v.z), c3 = __cosf(v.w);
        float c01 = c0 * c1, c012 = c01 * c2;
        out[i] = make_float4(c1 * c2 * c3, c01, c012, c012 * c3);
    }
}

extern "C" void kernel_launch(void* const* d_in, const int* in_sizes, int n_in,
                              void* d_out, int out_size)
{
    const float4* x = (const float4*)d_in[0];   // x: [B,4] float32
    float4* out = (float4*)d_out;               // out: [B,4] float32
    int n4 = in_sizes[0] / 4;                   // float4 count
    int grid = n4 / F4_PER_BLOCK;
    if (grid > 0)
        _VariationalQHead_65481071396152_kernel<<<grid, BLOCK>>>(x, out);
    int rem_start = grid * F4_PER_BLOCK;
    int rem = n4 - rem_start;
    if (rem > 0)
        _VQH_tail_kernel<<<(rem + 255) / 256, 256>>>(x, out, rem_start, n4);
}